// round 3
// baseline (speedup 1.0000x reference)
#include <cuda_runtime.h>
#include <math.h>

#define BB 8
#define CC 256
#define TT 16
#define HWN 1024
#define CR 16
#define TILES 32
#define THW 32   // hw columns per K1 tile

// ---------------- scratch (device globals; no allocation) -------------------
__device__ float g_hid[BB * CR * HWN];            // post-ReLU spatial hidden [b][r][hw]
__device__ float g_tp_part[TILES * BB * CC * TT]; // temporal pool partial sums (over 32 hw)
__device__ float g_comb[BB * CC * TT];            // temporal_att * channel_att

__device__ __forceinline__ float sigmoidf(float a) {
    return 1.0f / (1.0f + __expf(-a));
}

// ---------------- K1: stream x -> spatial hidden + tp partials ---------------
// grid = BB*TILES (256), 256 threads, 64KB dyn smem.
// smem: w1s[CR*CC]=4096  sp_s[CC*THW]=8192  tp_s[CC*TT]=4096  (16384 f = 64KB)
#define K1_SMEM_FLOATS (CR * CC + CC * THW + CC * TT)

__global__ void pool_hid_kernel(const float* __restrict__ x,
                                const float* __restrict__ ws1,
                                const float* __restrict__ bs1) {
    extern __shared__ float sm[];
    float* w1s  = sm;               // [r][c]
    float* sp_s = w1s + CR * CC;    // [c][hw_l]  (mean over t)
    float* tp_s = sp_s + CC * THW;  // [c][t]     (sum over 32 hw)

    const int bx   = blockIdx.x;
    const int b    = bx >> 5;
    const int tile = bx & 31;
    const int hw0  = tile * THW;
    const int tid  = threadIdx.x;

    for (int i = tid; i < CR * CC; i += 256) w1s[i] = ws1[i];

    const int f4 = tid & 7;   // float4 lane within 32-float hw window
    const int cg = tid >> 3;  // 0..31 channel group
    const float4* xb = (const float4*)(x + (size_t)b * CC * TT * HWN);

#pragma unroll
    for (int i = 0; i < 8; i++) {
        const int c = cg * 8 + i;
        float4 spv = make_float4(0.f, 0.f, 0.f, 0.f);
        float ts[TT];
#pragma unroll
        for (int t = 0; t < TT; t++) {
            float4 v = xb[(size_t)(c * TT + t) * (HWN / 4) + (hw0 >> 2) + f4];
            spv.x += v.x; spv.y += v.y; spv.z += v.z; spv.w += v.w;
            ts[t] = (v.x + v.y) + (v.z + v.w);
        }
        float4* spd = (float4*)(sp_s + c * THW);
        float4 spo;
        spo.x = spv.x * (1.f / TT); spo.y = spv.y * (1.f / TT);
        spo.z = spv.z * (1.f / TT); spo.w = spv.w * (1.f / TT);
        spd[f4] = spo;
#pragma unroll
        for (int t = 0; t < TT; t++) {
            float s = ts[t];
            s += __shfl_down_sync(0xffffffffu, s, 4, 8);
            s += __shfl_down_sync(0xffffffffu, s, 2, 8);
            s += __shfl_down_sync(0xffffffffu, s, 1, 8);
            if (f4 == 0) tp_s[c * TT + t] = s;   // sum over 32 hw
        }
    }
    __syncthreads();

    // first SE layer: hidden[r][hw_l] = relu(b1 + sum_c w1[r,c]*sp[c,hw_l])
    const int hw_l = tid & 31;
    const int rg   = tid >> 5;          // 0..7 -> rows rg*2, rg*2+1
    const int r0   = rg * 2, r1 = rg * 2 + 1;
    float a0 = bs1[r0], a1 = bs1[r1];
#pragma unroll 8
    for (int c = 0; c < CC; c++) {
        const float v = sp_s[c * THW + hw_l];
        a0 = fmaf(w1s[r0 * CC + c], v, a0);
        a1 = fmaf(w1s[r1 * CC + c], v, a1);
    }
    g_hid[(b * CR + r0) * HWN + hw0 + hw_l] = fmaxf(a0, 0.f);
    g_hid[(b * CR + r1) * HWN + hw0 + hw_l] = fmaxf(a1, 0.f);

    // temporal pool partials out (coalesced)
    float* tpp = g_tp_part + ((size_t)tile * BB + b) * (CC * TT);
    for (int i = tid; i < CC * TT; i += 256) tpp[i] = tp_s[i];
}

// ---------------- K2: temporal + channel SE -> comb --------------------------
// one block per b; 256 threads (== C)
__global__ void small_se_kernel(const float* __restrict__ wt1, const float* __restrict__ bt1,
                                const float* __restrict__ wt2, const float* __restrict__ bt2,
                                const float* __restrict__ wc1, const float* __restrict__ bc1,
                                const float* __restrict__ wc2, const float* __restrict__ bc2) {
    __shared__ float tps[CC * TT];  // temporal means [c][t]
    __shared__ float cps[CC];       // channel means
    __shared__ float ht[TT * CR];   // temporal hidden [t][r]
    __shared__ float hc[CR];        // channel hidden

    const int b   = blockIdx.x;
    const int tid = threadIdx.x;
    const int c   = tid;

    // sum 32 tile-partials for this (b,c)
    float4 acc[4];
#pragma unroll
    for (int j = 0; j < 4; j++) acc[j] = make_float4(0.f, 0.f, 0.f, 0.f);
    for (int tile = 0; tile < TILES; tile++) {
        const float4* p = (const float4*)(g_tp_part +
                          ((size_t)tile * BB + b) * (CC * TT) + c * TT);
#pragma unroll
        for (int j = 0; j < 4; j++) {
            float4 v = p[j];
            acc[j].x += v.x; acc[j].y += v.y; acc[j].z += v.z; acc[j].w += v.w;
        }
    }
    float cpsum = 0.f;
#pragma unroll
    for (int j = 0; j < 4; j++) {
        float4 m;
        m.x = acc[j].x * (1.f / HWN); m.y = acc[j].y * (1.f / HWN);
        m.z = acc[j].z * (1.f / HWN); m.w = acc[j].w * (1.f / HWN);
        ((float4*)(tps + c * TT))[j] = m;
        cpsum += (m.x + m.y) + (m.z + m.w);
    }
    cps[c] = cpsum * (1.f / TT);
    __syncthreads();

    // temporal hidden: thread -> (t, r)
    {
        const int t = tid >> 4;
        const int r = tid & 15;
        float s = bt1[r];
        for (int cc = 0; cc < CC; cc++)
            s = fmaf(wt1[r * CC + cc], tps[cc * TT + t], s);
        ht[t * CR + r] = fmaxf(s, 0.f);
    }
    if (tid < CR) {
        float s = bc1[tid];
        for (int cc = 0; cc < CC; cc++)
            s = fmaf(wc1[tid * CC + cc], cps[cc], s);
        hc[tid] = fmaxf(s, 0.f);
    }
    __syncthreads();

    // second layer per channel
    float ac = bc2[c];
#pragma unroll
    for (int r = 0; r < CR; r++) ac = fmaf(wc2[c * CR + r], hc[r], ac);
    const float sc = sigmoidf(ac);

    float w2r[CR];
#pragma unroll
    for (int r = 0; r < CR; r++) w2r[r] = wt2[c * CR + r];
    const float bt = bt2[c];
#pragma unroll
    for (int t = 0; t < TT; t++) {
        float at = bt;
#pragma unroll
        for (int r = 0; r < CR; r++) at = fmaf(w2r[r], ht[t * CR + r], at);
        g_comb[(b * CC + c) * TT + t] = sigmoidf(at) * sc;
    }
}

// ---------------- K3: apply (spatial att reconstructed from hid) -------------
// one block per (b,c); 256 threads
__global__ void apply_kernel(const float* __restrict__ x,
                             const float* __restrict__ ws2,
                             const float* __restrict__ bs2,
                             float* __restrict__ out) {
    const int bc  = blockIdx.x;
    const int b   = bc >> 8;
    const int c   = bc & 255;
    const int tid = threadIdx.x;

    __shared__ float combs[TT];
    __shared__ float w2s[CR];
    if (tid < TT) combs[tid] = g_comb[bc * TT + tid];
    if (tid >= 32 && tid < 32 + CR) w2s[tid - 32] = ws2[c * CR + (tid - 32)];
    __syncthreads();

    // spatial att for this thread's 4 hw positions
    const float b2 = bs2[c];
    float4 a = make_float4(b2, b2, b2, b2);
    const float4* hp = (const float4*)(g_hid + (size_t)b * CR * HWN);
#pragma unroll
    for (int r = 0; r < CR; r++) {
        const float4 h = hp[r * (HWN / 4) + tid];
        const float w = w2s[r];
        a.x = fmaf(w, h.x, a.x);
        a.y = fmaf(w, h.y, a.y);
        a.z = fmaf(w, h.z, a.z);
        a.w = fmaf(w, h.w, a.w);
    }
    a.x = sigmoidf(a.x); a.y = sigmoidf(a.y);
    a.z = sigmoidf(a.z); a.w = sigmoidf(a.w);

    const float4* xp = (const float4*)(x + (size_t)bc * (TT * HWN));
    float4* op       = (float4*)(out + (size_t)bc * (TT * HWN));
#pragma unroll
    for (int t = 0; t < TT; t++) {
        const float s = combs[t];
        float4 v = xp[t * (HWN / 4) + tid];
        v.x = v.x * a.x * s;
        v.y = v.y * a.y * s;
        v.z = v.z * a.z * s;
        v.w = v.w * a.w * s;
        op[t * (HWN / 4) + tid] = v;
    }
}

// ---------------- launch -----------------------------------------------------
extern "C" void kernel_launch(void* const* d_in, const int* in_sizes, int n_in,
                              void* d_out, int out_size) {
    const float* x   = (const float*)d_in[0];
    const float* ws1 = (const float*)d_in[1];
    const float* bs1 = (const float*)d_in[2];
    const float* ws2 = (const float*)d_in[3];
    const float* bs2 = (const float*)d_in[4];
    const float* wt1 = (const float*)d_in[5];
    const float* bt1 = (const float*)d_in[6];
    const float* wt2 = (const float*)d_in[7];
    const float* bt2 = (const float*)d_in[8];
    const float* wc1 = (const float*)d_in[9];
    const float* bc1 = (const float*)d_in[10];
    const float* wc2 = (const float*)d_in[11];
    const float* bc2 = (const float*)d_in[12];
    float* out = (float*)d_out;

    const int k1_smem = K1_SMEM_FLOATS * (int)sizeof(float);
    cudaFuncSetAttribute(pool_hid_kernel,
                         cudaFuncAttributeMaxDynamicSharedMemorySize, k1_smem);
    pool_hid_kernel<<<BB * TILES, 256, k1_smem>>>(x, ws1, bs1);
    small_se_kernel<<<BB, 256>>>(wt1, bt1, wt2, bt2, wc1, bc1, wc2, bc2);
    apply_kernel<<<BB * CC, 256>>>(x, ws2, bs2, out);
}

// round 4
// speedup vs baseline: 1.0704x; 1.0704x over previous
#include <cuda_runtime.h>
#include <math.h>

#define BB 8
#define CC 256
#define TT 16
#define HWN 1024
#define CR 16

// ---------------- scratch (device globals; no allocation) -------------------
__device__ float g_sp[BB * CC * HWN];   // spatial pooled mean  [b, c, hw]
__device__ float g_tp[BB * CC * TT];    // temporal pooled mean [b, c, t]
__device__ float g_cp[BB * CC];         // channel pooled mean  [b, c]
__device__ float g_comb[BB * CC * TT];  // temporal_att * channel_att
__device__ float g_att[BB * CC * HWN];  // spatial attention    [b, c, hw]

__device__ __forceinline__ float sigmoidf(float a) {
    return 1.0f / (1.0f + __expf(-a));
}

// ---------------- K1: pooling -----------------------------------------------
// one block per (b,c); 256 threads; float4 loads.
__global__ void pool_kernel(const float* __restrict__ x) {
    const int bc  = blockIdx.x;
    const int tid = threadIdx.x;
    const float4* xb = (const float4*)(x + (size_t)bc * (TT * HWN));

    float4 sp = make_float4(0.f, 0.f, 0.f, 0.f);
    float tpar[TT];

#pragma unroll
    for (int t = 0; t < TT; t++) {
        float4 v = xb[t * (HWN / 4) + tid];
        sp.x += v.x; sp.y += v.y; sp.z += v.z; sp.w += v.w;
        tpar[t] = (v.x + v.y) + (v.z + v.w);
    }

    float4 spo;
    spo.x = sp.x * (1.f / TT); spo.y = sp.y * (1.f / TT);
    spo.z = sp.z * (1.f / TT); spo.w = sp.w * (1.f / TT);
    ((float4*)(g_sp + (size_t)bc * HWN))[tid] = spo;

    __shared__ float wsum[8][TT];
    const int lane = tid & 31;
    const int wid  = tid >> 5;
#pragma unroll
    for (int t = 0; t < TT; t++) {
        float s = tpar[t];
#pragma unroll
        for (int off = 16; off > 0; off >>= 1)
            s += __shfl_down_sync(0xffffffffu, s, off);
        if (lane == 0) wsum[wid][t] = s;
    }
    __syncthreads();
    if (tid < TT) {
        float s = 0.f;
#pragma unroll
        for (int w = 0; w < 8; w++) s += wsum[w][tid];
        g_tp[bc * TT + tid] = s * (1.f / HWN);
        wsum[0][tid] = s;
    }
    __syncthreads();
    if (tid == 0) {
        float tot = 0.f;
#pragma unroll
        for (int t = 0; t < TT; t++) tot += wsum[0][t];
        g_cp[bc] = tot * (1.f / (TT * HWN));
    }
}

// ---------------- K2: temporal + channel SE -> comb --------------------------
// one block per (b,t); 256 threads (== C)
__global__ void small_se_kernel(const float* __restrict__ wt1, const float* __restrict__ bt1,
                                const float* __restrict__ wt2, const float* __restrict__ bt2,
                                const float* __restrict__ wc1, const float* __restrict__ bc1,
                                const float* __restrict__ wc2, const float* __restrict__ bc2) {
    const int b   = blockIdx.x >> 4;
    const int t   = blockIdx.x & 15;
    const int tid = threadIdx.x;

    __shared__ float pt[CC], pc[CC], hids[2 * CR];

    pt[tid] = g_tp[(b * CC + tid) * TT + t];
    pc[tid] = g_cp[b * CC + tid];
    __syncthreads();

    if (tid < CR) {
        float s = bt1[tid];
        for (int c = 0; c < CC; c++) s = fmaf(wt1[tid * CC + c], pt[c], s);
        hids[tid] = fmaxf(s, 0.f);
    } else if (tid < 2 * CR) {
        const int r = tid - CR;
        float s = bc1[r];
        for (int c = 0; c < CC; c++) s = fmaf(wc1[r * CC + c], pc[c], s);
        hids[tid] = fmaxf(s, 0.f);
    }
    __syncthreads();

    float at = bt2[tid];
    float ac = bc2[tid];
#pragma unroll
    for (int r = 0; r < CR; r++) {
        at = fmaf(wt2[tid * CR + r], hids[r],      at);
        ac = fmaf(wc2[tid * CR + r], hids[CR + r], ac);
    }
    g_comb[(b * CC + tid) * TT + t] = sigmoidf(at) * sigmoidf(ac);
}

// ---------------- K3: spatial SE: g_sp -> g_att ------------------------------
// grid = BB * (HWN/64) = 128 blocks, 256 threads.
// block owns (b, 64-hw window); 4-way channel split.
// dyn smem floats: w1s[4096] w2s[4096] stage[4][16][64]=4096 hidf[16][64]=1024
//                  b2s[256] b1s[16]  => 13584 f = 54336 B
#define K3_SMEM_FLOATS (CR * CC + CC * CR + 4 * CR * 64 + CR * 64 + CC + CR)

__global__ void att_kernel(const float* __restrict__ ws1, const float* __restrict__ bs1,
                           const float* __restrict__ ws2, const float* __restrict__ bs2) {
    extern __shared__ float sm[];
    float* w1s   = sm;                  // [r][c]
    float* w2s   = w1s + CR * CC;       // [c][r]
    float* stage = w2s + CC * CR;       // [q][r][64]
    float* hidf  = stage + 4 * CR * 64; // [r][64]
    float* b2s   = hidf + CR * 64;      // [256]
    float* b1s   = b2s + CC;            // [16]

    const int bx   = blockIdx.x;
    const int b    = bx >> 4;
    const int hw0  = (bx & 15) * 64;
    const int tid  = threadIdx.x;
    const int hw_l = tid & 63;   // 0..63
    const int cq   = tid >> 6;   // 0..3 -> channels cq*64 .. cq*64+63

    for (int i = tid; i < CR * CC; i += 256) { w1s[i] = ws1[i]; w2s[i] = ws2[i]; }
    if (tid < CC) b2s[tid] = bs2[tid];
    if (tid < CR) b1s[tid] = bs1[tid];
    __syncthreads();

    // phase 1: partial hidden over this thread's 64 channels
    float h[CR];
#pragma unroll
    for (int r = 0; r < CR; r++) h[r] = 0.f;

    const float* spb = g_sp + (size_t)(b * CC) * HWN + hw0 + hw_l;
#pragma unroll 4
    for (int i = 0; i < 64; i++) {
        const int c = cq * 64 + i;
        const float v = spb[(size_t)c * HWN];
#pragma unroll
        for (int r = 0; r < CR; r++) h[r] = fmaf(w1s[r * CC + c], v, h[r]);
    }
#pragma unroll
    for (int r = 0; r < CR; r++) stage[(cq * CR + r) * 64 + hw_l] = h[r];
    __syncthreads();

    // reduce 4 partials + ReLU: each thread handles 4 (r, hw_l) pairs
#pragma unroll
    for (int i = 0; i < 4; i++) {
        const int r = cq + 4 * i;
        float s = b1s[r];
#pragma unroll
        for (int q = 0; q < 4; q++) s += stage[(q * CR + r) * 64 + hw_l];
        hidf[r * 64 + hw_l] = fmaxf(s, 0.f);
    }
    __syncthreads();

    // phase 2: attention for this thread's 64 channels
    float hv[CR];
#pragma unroll
    for (int r = 0; r < CR; r++) hv[r] = hidf[r * 64 + hw_l];

    float* attb = g_att + (size_t)(b * CC) * HWN + hw0 + hw_l;
#pragma unroll 4
    for (int i = 0; i < 64; i++) {
        const int c = cq * 64 + i;
        float a = b2s[c];
#pragma unroll
        for (int r = 0; r < CR; r++) a = fmaf(w2s[c * CR + r], hv[r], a);
        attb[(size_t)c * HWN] = sigmoidf(a);
    }
}

// ---------------- K4: pure streaming apply ----------------------------------
// one block per (b,c); 256 threads
__global__ void apply_kernel(const float* __restrict__ x, float* __restrict__ out) {
    const int bc  = blockIdx.x;
    const int tid = threadIdx.x;

    __shared__ float combs[TT];
    if (tid < TT) combs[tid] = g_comb[bc * TT + tid];

    const float4 a = ((const float4*)(g_att + (size_t)bc * HWN))[tid];
    __syncthreads();

    const float4* xp = (const float4*)(x + (size_t)bc * (TT * HWN));
    float4* op       = (float4*)(out + (size_t)bc * (TT * HWN));

#pragma unroll
    for (int t = 0; t < TT; t++) {
        const float s = combs[t];
        float4 v = xp[t * (HWN / 4) + tid];
        v.x = v.x * a.x * s;
        v.y = v.y * a.y * s;
        v.z = v.z * a.z * s;
        v.w = v.w * a.w * s;
        op[t * (HWN / 4) + tid] = v;
    }
}

// ---------------- launch -----------------------------------------------------
extern "C" void kernel_launch(void* const* d_in, const int* in_sizes, int n_in,
                              void* d_out, int out_size) {
    const float* x   = (const float*)d_in[0];
    const float* ws1 = (const float*)d_in[1];
    const float* bs1 = (const float*)d_in[2];
    const float* ws2 = (const float*)d_in[3];
    const float* bs2 = (const float*)d_in[4];
    const float* wt1 = (const float*)d_in[5];
    const float* bt1 = (const float*)d_in[6];
    const float* wt2 = (const float*)d_in[7];
    const float* bt2 = (const float*)d_in[8];
    const float* wc1 = (const float*)d_in[9];
    const float* bc1 = (const float*)d_in[10];
    const float* wc2 = (const float*)d_in[11];
    const float* bc2 = (const float*)d_in[12];
    float* out = (float*)d_out;

    pool_kernel<<<BB * CC, 256>>>(x);
    small_se_kernel<<<BB * TT, 256>>>(wt1, bt1, wt2, bt2, wc1, bc1, wc2, bc2);

    const int k3_smem = K3_SMEM_FLOATS * (int)sizeof(float);
    cudaFuncSetAttribute(att_kernel,
                         cudaFuncAttributeMaxDynamicSharedMemorySize, k3_smem);
    att_kernel<<<BB * (HWN / 64), 256, k3_smem>>>(ws1, bs1, ws2, bs2);

    apply_kernel<<<BB * CC, 256>>>(x, out);
}

// round 5
// speedup vs baseline: 1.1845x; 1.1066x over previous
#include <cuda_runtime.h>
#include <math.h>

#define BB 8
#define CC 256
#define TT 16
#define HWN 1024
#define CR 16

// ---------------- scratch (device globals; no allocation) -------------------
__device__ float g_hid_part[4 * BB * CR * HWN];       // partial hidden per c-split (2MB)
__device__ float g_tp_part[BB * CC * 32 * TT];        // tp partials [b][c][tile][t] (4MB)
__device__ float g_hid[BB * CR * HWN];                // post-ReLU spatial hidden (512KB)
__device__ float g_tp[BB * CC * TT];                  // temporal pooled mean
__device__ float g_cp[BB * CC];                       // channel pooled mean
__device__ float g_comb[BB * CC * TT];                // temporal_att * channel_att

__device__ __forceinline__ float sigmoidf(float a) {
    return 1.0f / (1.0f + __expf(-a));
}

// ---------------- K1: stream x once -> hid partials + tp partials ------------
// grid = BB * 32tiles * 4csplits = 1024 blocks, 256 threads, ~16KB smem.
__global__ void pool_hid_kernel(const float* __restrict__ x,
                                const float* __restrict__ ws1) {
    __shared__ float w1s[CR * 64];    // [r][c_local]       4KB
    __shared__ float sp_s[64 * 32];   // [c_local][hw_l]    8KB
    __shared__ float tp_s[64 * TT];   // [c_local][t]       4KB

    const int bx   = blockIdx.x;
    const int q    = bx & 3;          // channel split 0..3
    const int tile = (bx >> 2) & 31;  // hw tile 0..31
    const int b    = bx >> 7;
    const int tid  = threadIdx.x;

    for (int i = tid; i < CR * 64; i += 256)
        w1s[i] = ws1[(i >> 6) * CC + q * 64 + (i & 63)];

    // phase A: pool. thread = (c_half 0..31, f4 0..7); 2 channels per thread
    const int f4  = tid & 7;
    const int cl2 = tid >> 3;
    const float4* xb = (const float4*)x;

#pragma unroll
    for (int i = 0; i < 2; i++) {
        const int c_local = cl2 + 32 * i;
        const int c = q * 64 + c_local;
        const size_t rowbase = (size_t)(b * CC + c) * TT * (HWN / 4) + tile * 8 + f4;
        float4 sp = make_float4(0.f, 0.f, 0.f, 0.f);
        float ts[TT];
#pragma unroll
        for (int t = 0; t < TT; t++) {
            float4 v = xb[rowbase + t * (HWN / 4)];
            sp.x += v.x; sp.y += v.y; sp.z += v.z; sp.w += v.w;
            ts[t] = (v.x + v.y) + (v.z + v.w);
        }
        float4 spo;
        spo.x = sp.x * (1.f / TT); spo.y = sp.y * (1.f / TT);
        spo.z = sp.z * (1.f / TT); spo.w = sp.w * (1.f / TT);
        ((float4*)(sp_s + c_local * 32))[f4] = spo;
#pragma unroll
        for (int t = 0; t < TT; t++) {
            float s = ts[t];
            s += __shfl_down_sync(0xffffffffu, s, 4, 8);
            s += __shfl_down_sync(0xffffffffu, s, 2, 8);
            s += __shfl_down_sync(0xffffffffu, s, 1, 8);
            if (f4 == 0) tp_s[c_local * TT + t] = s;  // sum over this tile's 32 hw
        }
    }
    __syncthreads();

    // phase B: partial hidden over this split's 64 channels
    const int hw_l = tid & 31;
    const int rg   = tid >> 5;
    const int r0   = rg * 2, r1 = r0 + 1;
    float a0 = 0.f, a1 = 0.f;
#pragma unroll 8
    for (int cl = 0; cl < 64; cl++) {
        const float v = sp_s[cl * 32 + hw_l];
        a0 = fmaf(w1s[r0 * 64 + cl], v, a0);
        a1 = fmaf(w1s[r1 * 64 + cl], v, a1);
    }
    float* hp = g_hid_part + (size_t)(q * BB + b) * CR * HWN + tile * 32 + hw_l;
    hp[(size_t)r0 * HWN] = a0;
    hp[(size_t)r1 * HWN] = a1;

    // phase C: tp partials out, layout [b][c][tile][t]
    if (tid < 64) {
        float4* dst = (float4*)(g_tp_part +
                      (size_t)((b * CC + q * 64 + tid) * 32 + tile) * TT);
        const float4* src = (const float4*)(tp_s + tid * TT);
        dst[0] = src[0]; dst[1] = src[1]; dst[2] = src[2]; dst[3] = src[3];
    }
}

// ---------------- K2: reductions (hid partials, tp partials) -----------------
// grid = 192: blocks [0,128) hid reduce (b,r); blocks [128,192) tp reduce.
__global__ void reduce_kernel(const float* __restrict__ bs1) {
    const int bi  = blockIdx.x;
    const int tid = threadIdx.x;

    if (bi < 128) {
        const int b = bi >> 4;
        const int r = bi & 15;
        float4 s = make_float4(0.f, 0.f, 0.f, 0.f);
#pragma unroll
        for (int q = 0; q < 4; q++) {
            float4 v = ((const float4*)(g_hid_part +
                        (size_t)(q * BB + b) * CR * HWN + (size_t)r * HWN))[tid];
            s.x += v.x; s.y += v.y; s.z += v.z; s.w += v.w;
        }
        const float bb = bs1[r];
        float4 o;
        o.x = fmaxf(s.x + bb, 0.f); o.y = fmaxf(s.y + bb, 0.f);
        o.z = fmaxf(s.z + bb, 0.f); o.w = fmaxf(s.w + bb, 0.f);
        ((float4*)(g_hid + (size_t)(b * CR + r) * HWN))[tid] = o;
    } else {
        const int idx = bi - 128;       // 0..63
        const int b   = idx >> 3;
        const int cg  = idx & 7;
        const int cl  = tid >> 3;       // 0..31
        const int l8  = tid & 7;        // 0..7 -> tiles l8*4 .. l8*4+3
        const int c   = cg * 32 + cl;

        const float4* base = (const float4*)(g_tp_part + (size_t)(b * CC + c) * 32 * TT);
        float arr[TT];
#pragma unroll
        for (int k = 0; k < TT; k++) arr[k] = 0.f;
#pragma unroll
        for (int tl = 0; tl < 4; tl++) {
            const int tile = l8 * 4 + tl;
#pragma unroll
            for (int j = 0; j < 4; j++) {
                float4 v = base[tile * 4 + j];
                arr[j * 4 + 0] += v.x; arr[j * 4 + 1] += v.y;
                arr[j * 4 + 2] += v.z; arr[j * 4 + 3] += v.w;
            }
        }
#pragma unroll
        for (int off = 4; off > 0; off >>= 1)
#pragma unroll
            for (int k = 0; k < TT; k++)
                arr[k] += __shfl_down_sync(0xffffffffu, arr[k], off, 8);

        if (l8 == 0) {
            float tot = 0.f;
            float* tpd = g_tp + (size_t)(b * CC + c) * TT;
#pragma unroll
            for (int k = 0; k < TT; k++) {
                const float m = arr[k] * (1.f / HWN);
                tpd[k] = m;
                tot += m;
            }
            g_cp[b * CC + c] = tot * (1.f / TT);
        }
    }
}

// ---------------- K3: temporal + channel SE -> comb --------------------------
// one block per (b,t); 256 threads (== C)
__global__ void small_se_kernel(const float* __restrict__ wt1, const float* __restrict__ bt1,
                                const float* __restrict__ wt2, const float* __restrict__ bt2,
                                const float* __restrict__ wc1, const float* __restrict__ bc1,
                                const float* __restrict__ wc2, const float* __restrict__ bc2) {
    const int b   = blockIdx.x >> 4;
    const int t   = blockIdx.x & 15;
    const int tid = threadIdx.x;

    __shared__ float pt[CC], pc[CC], hids[2 * CR];

    pt[tid] = g_tp[(b * CC + tid) * TT + t];
    pc[tid] = g_cp[b * CC + tid];
    __syncthreads();

    if (tid < CR) {
        float s = bt1[tid];
        for (int c = 0; c < CC; c++) s = fmaf(wt1[tid * CC + c], pt[c], s);
        hids[tid] = fmaxf(s, 0.f);
    } else if (tid < 2 * CR) {
        const int r = tid - CR;
        float s = bc1[r];
        for (int c = 0; c < CC; c++) s = fmaf(wc1[r * CC + c], pc[c], s);
        hids[tid] = fmaxf(s, 0.f);
    }
    __syncthreads();

    float at = bt2[tid];
    float ac = bc2[tid];
#pragma unroll
    for (int r = 0; r < CR; r++) {
        at = fmaf(wt2[tid * CR + r], hids[r],      at);
        ac = fmaf(wc2[tid * CR + r], hids[CR + r], ac);
    }
    g_comb[(b * CC + tid) * TT + t] = sigmoidf(at) * sigmoidf(ac);
}

// ---------------- K4: apply (spatial att reconstructed from hid) -------------
// one block per (b,c); 256 threads
__global__ void apply_kernel(const float* __restrict__ x,
                             const float* __restrict__ ws2,
                             const float* __restrict__ bs2,
                             float* __restrict__ out) {
    const int bc  = blockIdx.x;
    const int b   = bc >> 8;
    const int c   = bc & 255;
    const int tid = threadIdx.x;

    __shared__ float combs[TT];
    __shared__ float w2s[CR];
    if (tid < TT) combs[tid] = g_comb[bc * TT + tid];
    if (tid >= 32 && tid < 32 + CR) w2s[tid - 32] = ws2[c * CR + (tid - 32)];
    __syncthreads();

    const float b2 = bs2[c];
    float4 a = make_float4(b2, b2, b2, b2);
    const float4* hp = (const float4*)(g_hid + (size_t)b * CR * HWN);
#pragma unroll
    for (int r = 0; r < CR; r++) {
        const float4 h = hp[r * (HWN / 4) + tid];
        const float w = w2s[r];
        a.x = fmaf(w, h.x, a.x);
        a.y = fmaf(w, h.y, a.y);
        a.z = fmaf(w, h.z, a.z);
        a.w = fmaf(w, h.w, a.w);
    }
    a.x = sigmoidf(a.x); a.y = sigmoidf(a.y);
    a.z = sigmoidf(a.z); a.w = sigmoidf(a.w);

    const float4* xp = (const float4*)(x + (size_t)bc * (TT * HWN));
    float4* op       = (float4*)(out + (size_t)bc * (TT * HWN));
#pragma unroll
    for (int t = 0; t < TT; t++) {
        const float s = combs[t];
        float4 v = xp[t * (HWN / 4) + tid];
        v.x = v.x * a.x * s;
        v.y = v.y * a.y * s;
        v.z = v.z * a.z * s;
        v.w = v.w * a.w * s;
        op[t * (HWN / 4) + tid] = v;
    }
}

// ---------------- launch -----------------------------------------------------
extern "C" void kernel_launch(void* const* d_in, const int* in_sizes, int n_in,
                              void* d_out, int out_size) {
    const float* x   = (const float*)d_in[0];
    const float* ws1 = (const float*)d_in[1];
    const float* bs1 = (const float*)d_in[2];
    const float* ws2 = (const float*)d_in[3];
    const float* bs2 = (const float*)d_in[4];
    const float* wt1 = (const float*)d_in[5];
    const float* bt1 = (const float*)d_in[6];
    const float* wt2 = (const float*)d_in[7];
    const float* bt2 = (const float*)d_in[8];
    const float* wc1 = (const float*)d_in[9];
    const float* bc1 = (const float*)d_in[10];
    const float* wc2 = (const float*)d_in[11];
    const float* bc2 = (const float*)d_in[12];
    float* out = (float*)d_out;

    pool_hid_kernel<<<BB * 32 * 4, 256>>>(x, ws1);
    reduce_kernel<<<192, 256>>>(bs1);
    small_se_kernel<<<BB * TT, 256>>>(wt1, bt1, wt2, bt2, wc1, bc1, wc2, bc2);
    apply_kernel<<<BB * CC, 256>>>(x, ws2, bs2, out);
}

// round 6
// speedup vs baseline: 1.2071x; 1.0191x over previous
#include <cuda_runtime.h>
#include <math.h>

#define BB 8
#define CC 256
#define TT 16
#define HWN 1024
#define CR 16

// ---------------- scratch (device globals; no allocation) -------------------
__device__ float g_hid_part[4 * BB * CR * HWN];  // partial hidden per c-split (2MB)
__device__ float g_tp_part[BB * CC * 32 * TT];   // tp partials [b][c][tile][t] (4MB)
__device__ float g_hid[BB * CR * HWN];           // post-ReLU spatial hidden (512KB)
__device__ float g_tp[BB * CC * TT];             // temporal pooled mean
__device__ float g_cp[BB * CC];                  // channel pooled mean
__device__ float g_comb[BB * CC * TT];           // temporal_att * channel_att
__device__ float g_att[BB * CC * HWN];           // spatial attention (8MB, L2-hot)

__device__ __forceinline__ float sigmoidf(float a) {
    return 1.0f / (1.0f + __expf(-a));
}

// ---------------- K1: stream x once -> hid partials + tp partials ------------
// grid = BB * 32tiles * 4csplits = 1024 blocks, 256 threads, 16KB smem.
__global__ void pool_hid_kernel(const float* __restrict__ x,
                                const float* __restrict__ ws1) {
    __shared__ float w1s[CR * 64];    // [r][c_local]
    __shared__ float sp_s[64 * 32];   // [c_local][hw_l]
    __shared__ float tp_s[64 * TT];   // [c_local][t]

    const int bx   = blockIdx.x;
    const int q    = bx & 3;
    const int tile = (bx >> 2) & 31;
    const int b    = bx >> 7;
    const int tid  = threadIdx.x;

    for (int i = tid; i < CR * 64; i += 256)
        w1s[i] = ws1[(i >> 6) * CC + q * 64 + (i & 63)];

    const int f4  = tid & 7;
    const int cl2 = tid >> 3;
    const float4* xb = (const float4*)x;

#pragma unroll
    for (int i = 0; i < 2; i++) {
        const int c_local = cl2 + 32 * i;
        const int c = q * 64 + c_local;
        const size_t rowbase = (size_t)(b * CC + c) * TT * (HWN / 4) + tile * 8 + f4;
        float4 sp = make_float4(0.f, 0.f, 0.f, 0.f);
        float ts[TT];
#pragma unroll
        for (int t = 0; t < TT; t++) {
            float4 v = xb[rowbase + t * (HWN / 4)];
            sp.x += v.x; sp.y += v.y; sp.z += v.z; sp.w += v.w;
            ts[t] = (v.x + v.y) + (v.z + v.w);
        }
        float4 spo;
        spo.x = sp.x * (1.f / TT); spo.y = sp.y * (1.f / TT);
        spo.z = sp.z * (1.f / TT); spo.w = sp.w * (1.f / TT);
        ((float4*)(sp_s + c_local * 32))[f4] = spo;
#pragma unroll
        for (int t = 0; t < TT; t++) {
            float s = ts[t];
            s += __shfl_down_sync(0xffffffffu, s, 4, 8);
            s += __shfl_down_sync(0xffffffffu, s, 2, 8);
            s += __shfl_down_sync(0xffffffffu, s, 1, 8);
            if (f4 == 0) tp_s[c_local * TT + t] = s;
        }
    }
    __syncthreads();

    const int hw_l = tid & 31;
    const int rg   = tid >> 5;
    const int r0   = rg * 2, r1 = r0 + 1;
    float a0 = 0.f, a1 = 0.f;
#pragma unroll 8
    for (int cl = 0; cl < 64; cl++) {
        const float v = sp_s[cl * 32 + hw_l];
        a0 = fmaf(w1s[r0 * 64 + cl], v, a0);
        a1 = fmaf(w1s[r1 * 64 + cl], v, a1);
    }
    float* hp = g_hid_part + (size_t)(q * BB + b) * CR * HWN + tile * 32 + hw_l;
    hp[(size_t)r0 * HWN] = a0;
    hp[(size_t)r1 * HWN] = a1;

    if (tid < 64) {
        float4* dst = (float4*)(g_tp_part +
                      (size_t)((b * CC + q * 64 + tid) * 32 + tile) * TT);
        const float4* src = (const float4*)(tp_s + tid * TT);
        dst[0] = src[0]; dst[1] = src[1]; dst[2] = src[2]; dst[3] = src[3];
    }
}

// ---------------- K2: reductions (hid partials, tp partials) -----------------
__global__ void reduce_kernel(const float* __restrict__ bs1) {
    const int bi  = blockIdx.x;
    const int tid = threadIdx.x;

    if (bi < 128) {
        const int b = bi >> 4;
        const int r = bi & 15;
        float4 s = make_float4(0.f, 0.f, 0.f, 0.f);
#pragma unroll
        for (int q = 0; q < 4; q++) {
            float4 v = ((const float4*)(g_hid_part +
                        (size_t)(q * BB + b) * CR * HWN + (size_t)r * HWN))[tid];
            s.x += v.x; s.y += v.y; s.z += v.z; s.w += v.w;
        }
        const float bb = bs1[r];
        float4 o;
        o.x = fmaxf(s.x + bb, 0.f); o.y = fmaxf(s.y + bb, 0.f);
        o.z = fmaxf(s.z + bb, 0.f); o.w = fmaxf(s.w + bb, 0.f);
        ((float4*)(g_hid + (size_t)(b * CR + r) * HWN))[tid] = o;
    } else {
        const int idx = bi - 128;
        const int b   = idx >> 3;
        const int cg  = idx & 7;
        const int cl  = tid >> 3;
        const int l8  = tid & 7;
        const int c   = cg * 32 + cl;

        const float4* base = (const float4*)(g_tp_part + (size_t)(b * CC + c) * 32 * TT);
        float arr[TT];
#pragma unroll
        for (int k = 0; k < TT; k++) arr[k] = 0.f;
#pragma unroll
        for (int tl = 0; tl < 4; tl++) {
            const int tile = l8 * 4 + tl;
#pragma unroll
            for (int j = 0; j < 4; j++) {
                float4 v = base[tile * 4 + j];
                arr[j * 4 + 0] += v.x; arr[j * 4 + 1] += v.y;
                arr[j * 4 + 2] += v.z; arr[j * 4 + 3] += v.w;
            }
        }
#pragma unroll
        for (int off = 4; off > 0; off >>= 1)
#pragma unroll
            for (int k = 0; k < TT; k++)
                arr[k] += __shfl_down_sync(0xffffffffu, arr[k], off, 8);

        if (l8 == 0) {
            float tot = 0.f;
            float* tpd = g_tp + (size_t)(b * CC + c) * TT;
#pragma unroll
            for (int k = 0; k < TT; k++) {
                const float m = arr[k] * (1.f / HWN);
                tpd[k] = m;
                tot += m;
            }
            g_cp[b * CC + c] = tot * (1.f / TT);
        }
    }
}

// ---------------- K3: mid kernel -- small SE (blocks<128) + spatial att ------
// grid = 384, 256 threads.
__global__ void mid_kernel(const float* __restrict__ wt1, const float* __restrict__ bt1,
                           const float* __restrict__ wt2, const float* __restrict__ bt2,
                           const float* __restrict__ wc1, const float* __restrict__ bc1,
                           const float* __restrict__ wc2, const float* __restrict__ bc2,
                           const float* __restrict__ ws2, const float* __restrict__ bs2) {
    const int tid = threadIdx.x;

    if (blockIdx.x < 128) {
        // ---- temporal + channel SE -> g_comb ----
        const int b = blockIdx.x >> 4;
        const int t = blockIdx.x & 15;

        __shared__ float pt[CC], pc[CC], hids[2 * CR];

        pt[tid] = g_tp[(b * CC + tid) * TT + t];
        pc[tid] = g_cp[b * CC + tid];
        __syncthreads();

        if (tid < CR) {
            float s = bt1[tid];
            for (int c = 0; c < CC; c++) s = fmaf(wt1[tid * CC + c], pt[c], s);
            hids[tid] = fmaxf(s, 0.f);
        } else if (tid < 2 * CR) {
            const int r = tid - CR;
            float s = bc1[r];
            for (int c = 0; c < CC; c++) s = fmaf(wc1[r * CC + c], pc[c], s);
            hids[tid] = fmaxf(s, 0.f);
        }
        __syncthreads();

        float at = bt2[tid];
        float ac = bc2[tid];
#pragma unroll
        for (int r = 0; r < CR; r++) {
            at = fmaf(wt2[tid * CR + r], hids[r],      at);
            ac = fmaf(wc2[tid * CR + r], hids[CR + r], ac);
        }
        g_comb[(b * CC + tid) * TT + t] = sigmoidf(at) * sigmoidf(ac);
    } else {
        // ---- spatial att: g_hid -> g_att, block = (b, 32-hw window) ----
        const int idx  = blockIdx.x - 128;   // 0..255
        const int b    = idx >> 5;
        const int hw0  = (idx & 31) * 32;
        const int c    = tid;                // 256 threads == 256 channels

        __shared__ float hids[CR * 32];      // [r][hw_l], read as broadcast
        for (int i = tid; i < CR * 32; i += 256)
            hids[i] = g_hid[(size_t)(b * CR + (i >> 5)) * HWN + hw0 + (i & 31)];

        float w2r[CR];
#pragma unroll
        for (int r = 0; r < CR; r++) w2r[r] = ws2[c * CR + r];
        const float b2 = bs2[c];
        __syncthreads();

        float4* attb = (float4*)(g_att + (size_t)(b * CC + c) * HWN + hw0);
#pragma unroll
        for (int h4 = 0; h4 < 8; h4++) {
            float4 a = make_float4(b2, b2, b2, b2);
#pragma unroll
            for (int r = 0; r < CR; r++) {
                const float4 h = ((const float4*)(hids + r * 32))[h4];
                const float w = w2r[r];
                a.x = fmaf(w, h.x, a.x);
                a.y = fmaf(w, h.y, a.y);
                a.z = fmaf(w, h.z, a.z);
                a.w = fmaf(w, h.w, a.w);
            }
            a.x = sigmoidf(a.x); a.y = sigmoidf(a.y);
            a.z = sigmoidf(a.z); a.w = sigmoidf(a.w);
            attb[h4] = a;
        }
    }
}

// ---------------- K4: pure streaming apply ----------------------------------
// one block per (b,c); 256 threads
__global__ void apply_kernel(const float* __restrict__ x, float* __restrict__ out) {
    const int bc  = blockIdx.x;
    const int tid = threadIdx.x;

    __shared__ float combs[TT];
    if (tid < TT) combs[tid] = g_comb[bc * TT + tid];

    const float4 a = ((const float4*)(g_att + (size_t)bc * HWN))[tid];
    __syncthreads();

    const float4* xp = (const float4*)(x + (size_t)bc * (TT * HWN));
    float4* op       = (float4*)(out + (size_t)bc * (TT * HWN));

#pragma unroll
    for (int t = 0; t < TT; t++) {
        const float s = combs[t];
        float4 v = xp[t * (HWN / 4) + tid];
        v.x = v.x * a.x * s;
        v.y = v.y * a.y * s;
        v.z = v.z * a.z * s;
        v.w = v.w * a.w * s;
        op[t * (HWN / 4) + tid] = v;
    }
}

// ---------------- launch -----------------------------------------------------
extern "C" void kernel_launch(void* const* d_in, const int* in_sizes, int n_in,
                              void* d_out, int out_size) {
    const float* x   = (const float*)d_in[0];
    const float* ws1 = (const float*)d_in[1];
    const float* bs1 = (const float*)d_in[2];
    const float* ws2 = (const float*)d_in[3];
    const float* bs2 = (const float*)d_in[4];
    const float* wt1 = (const float*)d_in[5];
    const float* bt1 = (const float*)d_in[6];
    const float* wt2 = (const float*)d_in[7];
    const float* bt2 = (const float*)d_in[8];
    const float* wc1 = (const float*)d_in[9];
    const float* bc1 = (const float*)d_in[10];
    const float* wc2 = (const float*)d_in[11];
    const float* bc2 = (const float*)d_in[12];
    float* out = (float*)d_out;

    pool_hid_kernel<<<BB * 32 * 4, 256>>>(x, ws1);
    reduce_kernel<<<192, 256>>>(bs1);
    mid_kernel<<<384, 256>>>(wt1, bt1, wt2, bt2, wc1, bc1, wc2, bc2, ws2, bs2);
    apply_kernel<<<BB * CC, 256>>>(x, out);
}